// round 10
// baseline (speedup 1.0000x reference)
#include <cuda_runtime.h>
#include <cuda_bf16.h>
#include <cstdint>
#include <math.h>

#define NU 40000
#define NI 40000
#define NN 40000
#define C 128
#define H 4
#define HD 32
#define E 200000
#define HSIZE (1 << 19)
#define HMASK (HSIZE - 1)

// ---------------- device scratch (static, no allocs) ----------------
__device__ int   g_ht_keys[4 * HSIZE];
__device__ int   g_ht_cnt [4 * HSIZE];
__device__ float g_proj[6 * NN * C];        // 0:Qu 1:Ku 2:Vu 3:Qi 4:Ki 5:Vi (fp32)
__device__ __nv_bfloat16 g_xb [2 * NN * C + 64 * C];   // bf16 x_user | x_item (+pad)
__device__ __nv_bfloat16 g_wb [4 * C * C];             // bf16 Wq Wk Wv Wo
__device__ __nv_bfloat16 g_aggb[2 * NN * C + 64 * C];  // bf16 attn aggregate (+pad)
__device__ int g_cnt_su[NN], g_cnt_du[NN], g_cnt_si[NN], g_cnt_di[NN];
__device__ int g_off0[NN], g_off1[NN];   // CSR offsets (rel0 dst=item, rel1 dst=user)
__device__ int g_cur0[NN], g_cur1[NN];   // scatter cursors
__device__ int    g_src_s[2 * E];        // CSR-sorted source ids
__device__ float4 g_bias4[2 * E];        // per-edge per-head score bias (precomputed)

// ---------------- helpers ----------------
__device__ __forceinline__ unsigned hash_key(int key) {
    unsigned h = (unsigned)key * 2654435761u;
    h ^= h >> 15;
    return h & HMASK;
}

__device__ __forceinline__ void ht_insert(int t, int key) {
    unsigned slot = hash_key(key);
    int* keys = g_ht_keys + t * HSIZE;
    int* cnts = g_ht_cnt + t * HSIZE;
    while (true) {
        int k = keys[slot];
        if (k == key) { atomicAdd(&cnts[slot], 1); return; }
        if (k == -1) {
            int old = atomicCAS(&keys[slot], -1, key);
            if (old == -1 || old == key) { atomicAdd(&cnts[slot], 1); return; }
        }
        slot = (slot + 1) & HMASK;
    }
}

__device__ __forceinline__ int ht_query(int t, int key) {
    unsigned slot = hash_key(key);
    const int* keys = g_ht_keys + t * HSIZE;
    const int* cnts = g_ht_cnt + t * HSIZE;
    while (true) {
        int k = keys[slot];
        if (k == key) return cnts[slot];
        if (k == -1) return 0;
        slot = (slot + 1) & HMASK;
    }
}

__device__ __forceinline__ void ldsm4(uint32_t& r0, uint32_t& r1, uint32_t& r2, uint32_t& r3,
                                      uint32_t addr) {
    asm volatile("ldmatrix.sync.aligned.m8n8.x4.shared.b16 {%0,%1,%2,%3}, [%4];"
                 : "=r"(r0), "=r"(r1), "=r"(r2), "=r"(r3) : "r"(addr));
}

__device__ __forceinline__ void mma_bf16(float* c, const uint32_t* a, const uint32_t* b) {
    asm volatile(
        "mma.sync.aligned.m16n8k16.row.col.f32.bf16.bf16.f32 "
        "{%0,%1,%2,%3}, {%4,%5,%6,%7}, {%8,%9}, {%0,%1,%2,%3};"
        : "+f"(c[0]), "+f"(c[1]), "+f"(c[2]), "+f"(c[3])
        : "r"(a[0]), "r"(a[1]), "r"(a[2]), "r"(a[3]), "r"(b[0]), "r"(b[1]));
}

// ---------------- kernels ----------------
// fp32 -> bf16 pre-conversion of x_user, x_item, and the 4 weight matrices
__global__ void convert_kernel(const float* __restrict__ xu, const float* __restrict__ xi,
                               const float* __restrict__ Wq, const float* __restrict__ Wk,
                               const float* __restrict__ Wv, const float* __restrict__ Wo) {
    int gid = blockIdx.x * blockDim.x + threadIdx.x;
    int T = gridDim.x * blockDim.x;
    const int NX = NN * C / 4;
    for (int i = gid; i < NX; i += T) {
        float4 a = *(const float4*)(xu + i * 4);
        float4 b = *(const float4*)(xi + i * 4);
        *(__nv_bfloat162*)(g_xb + i * 4)              = __float22bfloat162_rn(make_float2(a.x, a.y));
        *(__nv_bfloat162*)(g_xb + i * 4 + 2)          = __float22bfloat162_rn(make_float2(a.z, a.w));
        *(__nv_bfloat162*)(g_xb + NN * C + i * 4)     = __float22bfloat162_rn(make_float2(b.x, b.y));
        *(__nv_bfloat162*)(g_xb + NN * C + i * 4 + 2) = __float22bfloat162_rn(make_float2(b.z, b.w));
    }
    const int NW = C * C / 4;   // 4096
    for (int i = gid; i < NW; i += T) {
        const float* ws[4] = { Wq, Wk, Wv, Wo };
        #pragma unroll
        for (int w = 0; w < 4; w++) {
            float4 a = *(const float4*)(ws[w] + i * 4);
            *(__nv_bfloat162*)(g_wb + w * C * C + i * 4)     = __float22bfloat162_rn(make_float2(a.x, a.y));
            *(__nv_bfloat162*)(g_wb + w * C * C + i * 4 + 2) = __float22bfloat162_rn(make_float2(a.z, a.w));
        }
    }
}

__global__ void clear_kernel() {
    int gid = blockIdx.x * blockDim.x + threadIdx.x;
    int T = gridDim.x * blockDim.x;
    for (int i = gid; i < 4 * HSIZE; i += T) { g_ht_keys[i] = -1; g_ht_cnt[i] = 0; }
    for (int i = gid; i < NN; i += T) {
        g_cnt_su[i] = 0; g_cnt_du[i] = 0; g_cnt_si[i] = 0; g_cnt_di[i] = 0;
        g_cur0[i] = 0; g_cur1[i] = 0;
    }
}

__global__ void build_ht_kernel(const int* __restrict__ eui, const int* __restrict__ eiu) {
    int e = blockIdx.x * blockDim.x + threadIdx.x;
    if (e >= 2 * E) return;
    if (e < E) {
        int su = eui[e], du = eui[e + E];
        ht_insert(0, su * NI + du);      // pid_ui multiset
        ht_insert(3, du * NU + su);      // rev pairs for iu relation
        atomicAdd(&g_cnt_su[su], 1);
        atomicAdd(&g_cnt_du[du], 1);
    } else {
        int i = e - E;
        int si = eiu[i], di = eiu[i + E];
        ht_insert(1, si * NU + di);      // pid_iu multiset
        ht_insert(2, di * NI + si);      // rev pairs for ui relation
        atomicAdd(&g_cnt_si[si], 1);
        atomicAdd(&g_cnt_di[di], 1);
    }
}

// exclusive prefix scan of per-dst degree -> CSR offsets. one block per relation.
__global__ __launch_bounds__(1024) void scan_kernel() {
    int which = blockIdx.x;
    const int* cnt = which ? g_cnt_di : g_cnt_du;
    int* off = which ? g_off1 : g_off0;
    __shared__ int wsum[32];
    __shared__ int carry;
    int tid = threadIdx.x, lane = tid & 31, wid = tid >> 5;
    if (tid == 0) carry = 0;
    __syncthreads();
    for (int base = 0; base < NN; base += 1024) {
        int i = base + tid;
        int v = (i < NN) ? cnt[i] : 0;
        int x = v;
        #pragma unroll
        for (int d = 1; d < 32; d <<= 1) {
            int y = __shfl_up_sync(0xffffffffu, x, d);
            if (lane >= d) x += y;
        }
        if (lane == 31) wsum[wid] = x;
        __syncthreads();
        if (wid == 0) {
            int s = wsum[lane];
            #pragma unroll
            for (int d = 1; d < 32; d <<= 1) {
                int y = __shfl_up_sync(0xffffffffu, s, d);
                if (lane >= d) s += y;
            }
            wsum[lane] = s;   // inclusive across warps
        }
        __syncthreads();
        int wprefix = (wid == 0) ? 0 : wsum[wid - 1];
        int excl = carry + wprefix + (x - v);
        if (i < NN) off[i] = excl;
        __syncthreads();
        if (tid == 0) carry += wsum[31];
        __syncthreads();
    }
}

// scatter edges into CSR order + precompute per-edge head bias float4
__global__ void scatter_kernel(const int* __restrict__ eui, const int* __restrict__ eiu,
                               const float* __restrict__ t_user, const float* __restrict__ t_item,
                               const float* __restrict__ hb, const float* __restrict__ beta,
                               const float* __restrict__ tau_raw,
                               const float* __restrict__ gamma, const float* __restrict__ delta) {
    int idx = blockIdx.x * blockDim.x + threadIdx.x;
    if (idx >= 2 * E) return;
    int r = (idx >= E) ? 1 : 0;
    int e = idx - r * E;
    const int* ei = r ? eiu : eui;
    int src = ei[e], dst = ei[e + E];
    int* cur = r ? g_cur1 : g_cur0;
    const int* off = r ? g_off1 : g_off0;
    int pos = off[dst] + atomicAdd(&cur[dst], 1);
    g_src_s[r * E + pos] = src;

    float ts = (r ? t_item : t_user)[src];
    float td = (r ? t_user : t_item)[dst];
    float dt = fabsf(td - ts) + 1e-6f;
    int pid = src * 40000 + dst;
    float cntf = (float)(ht_query(r, pid) - 1);
    float recf = (ht_query(2 + r, pid) > 0) ? 1.f : 0.f;
    float tau = log1pf(expf(tau_raw[r])) + 1e-6f;
    float a = -log1pf(dt / tau);
    float b = log1pf(cntf);
    float4 bias;
    bias.x = hb[r * H + 0] + a * beta[r * H + 0] + b * gamma[r * H + 0] + recf * delta[r * H + 0];
    bias.y = hb[r * H + 1] + a * beta[r * H + 1] + b * gamma[r * H + 1] + recf * delta[r * H + 1];
    bias.z = hb[r * H + 2] + a * beta[r * H + 2] + b * gamma[r * H + 2] + recf * delta[r * H + 2];
    bias.w = hb[r * H + 3] + a * beta[r * H + 3] + b * gamma[r * H + 3] + recf * delta[r * H + 3];
    g_bias4[r * E + pos] = bias;
}

// fused edge attention: warp per destination, online softmax + weighted-V accumulate.
// processes 2 edges per iteration for MLP; writes aggregate as bf16.
__global__ __launch_bounds__(256) void attn_kernel() {
    int n = (blockIdx.x * blockDim.x + threadIdx.x) >> 5;
    int lane = threadIdx.x & 31;
    int r = blockIdx.y;
    if (n >= NN) return;

    const float* Q     = g_proj + (size_t)(r == 0 ? 3 : 0) * NN * C + (size_t)n * C;
    const float* Kbase = g_proj + (size_t)(r == 0 ? 1 : 4) * NN * C;
    const float* Vbase = g_proj + (size_t)(r == 0 ? 2 : 5) * NN * C;
    const int* off = r ? g_off1 : g_off0;
    int s0 = off[n];
    int s1 = (n + 1 < NN) ? off[n + 1] : E;
    const int* srcs = g_src_s + r * E;
    const float4* bias = g_bias4 + r * E;

    float4 q = *(const float4*)(Q + lane * 4);
    int h = lane >> 3;

    float m = -INFINITY, z = 0.f;
    float a0 = 0.f, a1 = 0.f, a2 = 0.f, a3 = 0.f;

    int j = s0;
    for (; j + 1 < s1; j += 2) {
        int sc0 = srcs[j], sc1 = srcs[j + 1];
        const float4 k0 = *(const float4*)(Kbase + (size_t)sc0 * C + lane * 4);
        const float4 k1 = *(const float4*)(Kbase + (size_t)sc1 * C + lane * 4);
        const float4 b40 = bias[j];
        const float4 b41 = bias[j + 1];
        const float4 v0 = *(const float4*)(Vbase + (size_t)sc0 * C + lane * 4);
        const float4 v1 = *(const float4*)(Vbase + (size_t)sc1 * C + lane * 4);

        float p0 = q.x * k0.x + q.y * k0.y + q.z * k0.z + q.w * k0.w;
        float p1 = q.x * k1.x + q.y * k1.y + q.z * k1.z + q.w * k1.w;
        p0 += __shfl_xor_sync(0xffffffffu, p0, 1);
        p1 += __shfl_xor_sync(0xffffffffu, p1, 1);
        p0 += __shfl_xor_sync(0xffffffffu, p0, 2);
        p1 += __shfl_xor_sync(0xffffffffu, p1, 2);
        p0 += __shfl_xor_sync(0xffffffffu, p0, 4);
        p1 += __shfl_xor_sync(0xffffffffu, p1, 4);

        float bh0 = (h == 0) ? b40.x : (h == 1) ? b40.y : (h == 2) ? b40.z : b40.w;
        float bh1 = (h == 0) ? b41.x : (h == 1) ? b41.y : (h == 2) ? b41.z : b41.w;
        float sA = p0 * 0.1767766952966369f + bh0;
        float sB = p1 * 0.1767766952966369f + bh1;

        float mn = fmaxf(m, fmaxf(sA, sB));
        float fac = __expf(m - mn);
        float e0 = __expf(sA - mn);
        float e1 = __expf(sB - mn);
        z = z * fac + e0 + e1;
        a0 = a0 * fac + e0 * v0.x + e1 * v1.x;
        a1 = a1 * fac + e0 * v0.y + e1 * v1.y;
        a2 = a2 * fac + e0 * v0.z + e1 * v1.z;
        a3 = a3 * fac + e0 * v0.w + e1 * v1.w;
        m = mn;
    }
    if (j < s1) {
        int sc0 = srcs[j];
        const float4 k0 = *(const float4*)(Kbase + (size_t)sc0 * C + lane * 4);
        const float4 b40 = bias[j];
        const float4 v0 = *(const float4*)(Vbase + (size_t)sc0 * C + lane * 4);
        float p0 = q.x * k0.x + q.y * k0.y + q.z * k0.z + q.w * k0.w;
        p0 += __shfl_xor_sync(0xffffffffu, p0, 1);
        p0 += __shfl_xor_sync(0xffffffffu, p0, 2);
        p0 += __shfl_xor_sync(0xffffffffu, p0, 4);
        float bh0 = (h == 0) ? b40.x : (h == 1) ? b40.y : (h == 2) ? b40.z : b40.w;
        float sA = p0 * 0.1767766952966369f + bh0;
        float mn = fmaxf(m, sA);
        float fac = __expf(m - mn);
        float e0 = __expf(sA - mn);
        z = z * fac + e0;
        a0 = a0 * fac + e0 * v0.x;
        a1 = a1 * fac + e0 * v0.y;
        a2 = a2 * fac + e0 * v0.z;
        a3 = a3 * fac + e0 * v0.w;
        m = mn;
    }

    float inv = (z > 0.f) ? 1.f / z : 0.f;
    __nv_bfloat16* ag = g_aggb + (size_t)r * NN * C + (size_t)n * C + lane * 4;
    *(__nv_bfloat162*)(ag)     = __float22bfloat162_rn(make_float2(a0 * inv, a1 * inv));
    *(__nv_bfloat162*)(ag + 2) = __float22bfloat162_rn(make_float2(a2 * inv, a3 * inv));
}

// ------------- bf16 tensor-core GEMM (bf16 inputs): C = A @ W^T (+bias) -------------
struct GemmJobB { const __nv_bfloat16* A; const __nv_bfloat16* W; const float* bias; float* out; };
struct GemmJobsB6 { GemmJobB j[6]; };

#define BSM_STRIDE 136   // bf16 elems per row: 17 x 16B -> ldmatrix conflict-free
#define BSM_BYTES (2 * 128 * BSM_STRIDE * 2)   // 69632 B

// shared tile loader: global bf16 [rows][128] -> smem [128][136]
__device__ __forceinline__ void load_tile_bf16(__nv_bfloat16* dstA, const __nv_bfloat16* A,
                                               __nv_bfloat16* dstW, const __nv_bfloat16* W,
                                               int tid) {
    #pragma unroll 4
    for (int i = tid; i < 128 * 16; i += 256) {
        int r = i >> 4, c8 = (i & 15) << 3;
        *(uint4*)(dstA + r * BSM_STRIDE + c8) = *(const uint4*)(A + r * 128 + c8);
        *(uint4*)(dstW + r * BSM_STRIDE + c8) = *(const uint4*)(W + r * 128 + c8);
    }
}

// core 128x128x128 compute from smem tiles
__device__ __forceinline__ void gemm_core(const __nv_bfloat16* As, const __nv_bfloat16* Ws,
                                          int warp, int lane, float acc[2][8][4]) {
    int wm = warp >> 1, wn = warp & 1;
    uint32_t sA = (uint32_t)__cvta_generic_to_shared(As);
    uint32_t sW = (uint32_t)__cvta_generic_to_shared(Ws);
    uint32_t aAddr[2], bAddr[4];
    #pragma unroll
    for (int mt = 0; mt < 2; mt++) {
        int row = wm * 32 + mt * 16 + (lane & 15);
        int col = (lane >> 4) << 3;
        aAddr[mt] = sA + (row * BSM_STRIDE + col) * 2;
    }
    #pragma unroll
    for (int ntp = 0; ntp < 4; ntp++) {
        int row = wn * 64 + ntp * 16 + ((lane >> 4) << 3) + (lane & 7);
        int col = ((lane >> 3) & 1) << 3;
        bAddr[ntp] = sW + (row * BSM_STRIDE + col) * 2;
    }
    #pragma unroll
    for (int ks = 0; ks < 8; ks++) {
        uint32_t koff = ks * 32;
        uint32_t a[2][4], b[8][2];
        ldsm4(a[0][0], a[0][1], a[0][2], a[0][3], aAddr[0] + koff);
        ldsm4(a[1][0], a[1][1], a[1][2], a[1][3], aAddr[1] + koff);
        #pragma unroll
        for (int ntp = 0; ntp < 4; ntp++)
            ldsm4(b[2 * ntp][0], b[2 * ntp][1], b[2 * ntp + 1][0], b[2 * ntp + 1][1],
                  bAddr[ntp] + koff);
        #pragma unroll
        for (int mt = 0; mt < 2; mt++)
            #pragma unroll
            for (int nt = 0; nt < 8; nt++)
                mma_bf16(acc[mt][nt], a[mt], b[nt]);
    }
}

__global__ __launch_bounds__(256) void gemm_bf16_kernel(GemmJobsB6 jobs, int M) {
    const GemmJobB jb = jobs.j[blockIdx.y];
    extern __shared__ __nv_bfloat16 shb[];
    __nv_bfloat16* As = shb;
    __nv_bfloat16* Ws = shb + 128 * BSM_STRIDE;
    int tid = threadIdx.x;
    int row0 = blockIdx.x * 128;

    load_tile_bf16(As, jb.A + (size_t)row0 * 128, Ws, jb.W, tid);
    __syncthreads();

    int warp = tid >> 5, lane = tid & 31;
    int wm = warp >> 1, wn = warp & 1;
    int g = lane >> 2, t4 = lane & 3;

    float acc[2][8][4];
    #pragma unroll
    for (int mt = 0; mt < 2; mt++)
        #pragma unroll
        for (int nt = 0; nt < 8; nt++)
            #pragma unroll
            for (int q = 0; q < 4; q++) acc[mt][nt][q] = 0.f;

    gemm_core(As, Ws, warp, lane, acc);

    #pragma unroll
    for (int mt = 0; mt < 2; mt++) {
        #pragma unroll
        for (int half = 0; half < 2; half++) {
            int row = row0 + wm * 32 + mt * 16 + g + half * 8;
            if (row >= M) continue;
            float* orow = jb.out + (size_t)row * 128 + wn * 64;
            #pragma unroll
            for (int nt = 0; nt < 8; nt++) {
                int col = nt * 8 + t4 * 2;
                float b0 = 0.f, b1 = 0.f;
                if (jb.bias) {
                    b0 = jb.bias[wn * 64 + col];
                    b1 = jb.bias[wn * 64 + col + 1];
                }
                float2 o = make_float2(acc[mt][nt][half * 2 + 0] + b0,
                                       acc[mt][nt][half * 2 + 1] + b1);
                *(float2*)(orow + col) = o;
            }
        }
    }
}

// O-projection GEMM with fused residual + degree bias + LayerNorm epilogue.
// blockIdx.y = relation (0: agg0 -> out_item, 1: agg1 -> out_user)
#define LN_STRIDE 132
__global__ __launch_bounds__(256) void ogemm_ln_kernel(const float* __restrict__ x_user,
                                                       const float* __restrict__ x_item,
                                                       const float* __restrict__ bo,
                                                       float* __restrict__ out) {
    int rel = blockIdx.y;
    extern __shared__ __nv_bfloat16 shb[];
    __nv_bfloat16* As = shb;
    __nv_bfloat16* Ws = shb + 128 * BSM_STRIDE;
    float* shf = (float*)shb;            // reused after compute: [128][132] fp32
    int tid = threadIdx.x;
    int row0 = blockIdx.x * 128;

    const __nv_bfloat16* A = g_aggb + (size_t)rel * NN * C;
    const __nv_bfloat16* W = g_wb + 3 * C * C;   // Wo

    load_tile_bf16(As, A + (size_t)row0 * 128, Ws, W, tid);
    __syncthreads();

    int warp = tid >> 5, lane = tid & 31;
    int wm = warp >> 1, wn = warp & 1;
    int g = lane >> 2, t4 = lane & 3;

    float acc[2][8][4];
    #pragma unroll
    for (int mt = 0; mt < 2; mt++)
        #pragma unroll
        for (int nt = 0; nt < 8; nt++)
            #pragma unroll
            for (int q = 0; q < 4; q++) acc[mt][nt][q] = 0.f;

    gemm_core(As, Ws, warp, lane, acc);
    __syncthreads();   // everyone done reading As/Ws -> reuse as fp32 LN buffer

    #pragma unroll
    for (int mt = 0; mt < 2; mt++) {
        #pragma unroll
        for (int half = 0; half < 2; half++) {
            int rl = wm * 32 + mt * 16 + g + half * 8;
            #pragma unroll
            for (int nt = 0; nt < 8; nt++) {
                int col = wn * 64 + nt * 8 + t4 * 2;
                shf[rl * LN_STRIDE + col]     = acc[mt][nt][half * 2 + 0];
                shf[rl * LN_STRIDE + col + 1] = acc[mt][nt][half * 2 + 1];
            }
        }
    }
    __syncthreads();

    // LN phase: each warp handles 16 rows
    const float* xres = rel ? x_user : x_item;
    float* obase = rel ? out : out + (size_t)NN * C;
    float4 bv = *(const float4*)(bo + lane * 4);
    for (int rr = 0; rr < 16; rr++) {
        int rl = warp * 16 + rr;
        int n = row0 + rl;
        if (n >= NN) continue;
        float indeg, deg;
        if (rel == 0) { indeg = (float)g_cnt_du[n]; deg = (float)(g_cnt_du[n] + g_cnt_si[n]); }
        else          { indeg = (float)g_cnt_di[n]; deg = (float)(g_cnt_su[n] + g_cnt_di[n]); }
        float4 v = *(float4*)(shf + rl * LN_STRIDE + lane * 4);
        float4 xv = *(const float4*)(xres + (size_t)n * C + lane * 4);
        v.x += xv.x + indeg * bv.x + deg;
        v.y += xv.y + indeg * bv.y + deg;
        v.z += xv.z + indeg * bv.z + deg;
        v.w += xv.w + indeg * bv.w + deg;
        float s = v.x + v.y + v.z + v.w;
        #pragma unroll
        for (int d = 16; d; d >>= 1) s += __shfl_xor_sync(0xffffffffu, s, d);
        float mu = s * (1.f / 128.f);
        float d0 = v.x - mu, d1 = v.y - mu, d2 = v.z - mu, d3 = v.w - mu;
        float qq = d0 * d0 + d1 * d1 + d2 * d2 + d3 * d3;
        #pragma unroll
        for (int d = 16; d; d >>= 1) qq += __shfl_xor_sync(0xffffffffu, qq, d);
        float inv = 1.f / sqrtf(qq * (1.f / 128.f) + 1e-5f);
        *(float4*)(obase + (size_t)n * C + lane * 4) =
            make_float4(d0 * inv, d1 * inv, d2 * inv, d3 * inv);
    }
}

// ---------------- launch ----------------
extern "C" void kernel_launch(void* const* d_in, const int* in_sizes, int n_in,
                              void* d_out, int out_size) {
    const float* x_user  = (const float*)d_in[0];
    const float* x_item  = (const float*)d_in[1];
    const float* t_user  = (const float*)d_in[2];
    const float* t_item  = (const float*)d_in[3];
    const int*   eui     = (const int*)d_in[4];
    const int*   eiu     = (const int*)d_in[5];
    const float* Wq      = (const float*)d_in[6];
    const float* bq      = (const float*)d_in[7];
    const float* Wk      = (const float*)d_in[8];
    const float* bk      = (const float*)d_in[9];
    const float* Wv      = (const float*)d_in[10];
    const float* bv      = (const float*)d_in[11];
    const float* Wo      = (const float*)d_in[12];
    const float* bo      = (const float*)d_in[13];
    const float* hb      = (const float*)d_in[14];
    const float* beta    = (const float*)d_in[15];
    const float* tau_raw = (const float*)d_in[16];
    const float* gammaP  = (const float*)d_in[17];
    const float* deltaP  = (const float*)d_in[18];
    float* out = (float*)d_out;

    float* proj;
    __nv_bfloat16 *xb, *wb;
    cudaGetSymbolAddress((void**)&proj, g_proj);
    cudaGetSymbolAddress((void**)&xb, g_xb);
    cudaGetSymbolAddress((void**)&wb, g_wb);

    cudaFuncSetAttribute(gemm_bf16_kernel,
                         cudaFuncAttributeMaxDynamicSharedMemorySize, BSM_BYTES);
    cudaFuncSetAttribute(ogemm_ln_kernel,
                         cudaFuncAttributeMaxDynamicSharedMemorySize, BSM_BYTES);

    // 1: convert  2: clear  3: build_ht  4: QKV gemm (profiled)  5: scan
    // 6: scatter  7: attn   8: O-gemm + LN
    convert_kernel<<<512, 256>>>(x_user, x_item, Wq, Wk, Wv, Wo);
    clear_kernel<<<512, 256>>>();
    build_ht_kernel<<<(2 * E + 255) / 256, 256>>>(eui, eiu);

    int gblocks = (NN + 127) / 128;   // 313

    GemmJobsB6 qkv;
    qkv.j[0] = { xb,          wb,             bq, proj + (size_t)0 * NN * C };
    qkv.j[1] = { xb,          wb + C * C,     bk, proj + (size_t)1 * NN * C };
    qkv.j[2] = { xb,          wb + 2 * C * C, bv, proj + (size_t)2 * NN * C };
    qkv.j[3] = { xb + NN * C, wb,             bq, proj + (size_t)3 * NN * C };
    qkv.j[4] = { xb + NN * C, wb + C * C,     bk, proj + (size_t)4 * NN * C };
    qkv.j[5] = { xb + NN * C, wb + 2 * C * C, bv, proj + (size_t)5 * NN * C };
    gemm_bf16_kernel<<<dim3(gblocks, 6), 256, BSM_BYTES>>>(qkv, NN);

    scan_kernel<<<2, 1024>>>();
    scatter_kernel<<<(2 * E + 255) / 256, 256>>>(eui, eiu, t_user, t_item,
                                                 hb, beta, tau_raw, gammaP, deltaP);

    dim3 agrid((NN * 32 + 255) / 256, 2);
    attn_kernel<<<agrid, 256>>>();

    ogemm_ln_kernel<<<dim3(gblocks, 2), 256, BSM_BYTES>>>(x_user, x_item, bo, out);
}

// round 11
// speedup vs baseline: 1.2151x; 1.2151x over previous
#include <cuda_runtime.h>
#include <cuda_bf16.h>
#include <cstdint>
#include <math.h>

#define NU 40000
#define NI 40000
#define NN 40000
#define C 128
#define H 4
#define HD 32
#define E 200000
#define HSIZE (1 << 19)
#define HMASK (HSIZE - 1)

// ---------------- device scratch (static, no allocs) ----------------
__device__ int   g_ht_keys[4 * HSIZE];
__device__ int   g_ht_cnt [4 * HSIZE];
__device__ float g_proj[6 * NN * C];        // 0:Qu 1:Ku 2:Vu 3:Qi 4:Ki 5:Vi (fp32)
__device__ __nv_bfloat16 g_xb [2 * NN * C + 64 * C];   // bf16 x_user | x_item (+pad)
__device__ __nv_bfloat16 g_wb [4 * C * C];             // bf16 Wq Wk Wv Wo
__device__ __nv_bfloat16 g_aggb[2 * NN * C + 64 * C];  // bf16 attn aggregate (+pad)
__device__ int g_cnt_su[NN], g_cnt_du[NN], g_cnt_si[NN], g_cnt_di[NN];
__device__ int g_off0[NN], g_off1[NN];   // CSR offsets (rel0 dst=item, rel1 dst=user)
__device__ int g_cur0[NN], g_cur1[NN];   // scatter cursors
__device__ int    g_src_s[2 * E];        // CSR-sorted source ids
__device__ float4 g_bias4[2 * E];        // per-edge per-head score bias (precomputed)

// ---------------- helpers ----------------
__device__ __forceinline__ unsigned hash_key(int key) {
    unsigned h = (unsigned)key * 2654435761u;
    h ^= h >> 15;
    return h & HMASK;
}

__device__ __forceinline__ void ht_insert(int t, int key) {
    unsigned slot = hash_key(key);
    int* keys = g_ht_keys + t * HSIZE;
    int* cnts = g_ht_cnt + t * HSIZE;
    while (true) {
        int k = keys[slot];
        if (k == key) { atomicAdd(&cnts[slot], 1); return; }
        if (k == -1) {
            int old = atomicCAS(&keys[slot], -1, key);
            if (old == -1 || old == key) { atomicAdd(&cnts[slot], 1); return; }
        }
        slot = (slot + 1) & HMASK;
    }
}

__device__ __forceinline__ int ht_query(int t, int key) {
    unsigned slot = hash_key(key);
    const int* keys = g_ht_keys + t * HSIZE;
    const int* cnts = g_ht_cnt + t * HSIZE;
    while (true) {
        int k = keys[slot];
        if (k == key) return cnts[slot];
        if (k == -1) return 0;
        slot = (slot + 1) & HMASK;
    }
}

__device__ __forceinline__ void ldsm4(uint32_t& r0, uint32_t& r1, uint32_t& r2, uint32_t& r3,
                                      uint32_t addr) {
    asm volatile("ldmatrix.sync.aligned.m8n8.x4.shared.b16 {%0,%1,%2,%3}, [%4];"
                 : "=r"(r0), "=r"(r1), "=r"(r2), "=r"(r3) : "r"(addr));
}

__device__ __forceinline__ void mma_bf16(float* c, const uint32_t* a, const uint32_t* b) {
    asm volatile(
        "mma.sync.aligned.m16n8k16.row.col.f32.bf16.bf16.f32 "
        "{%0,%1,%2,%3}, {%4,%5,%6,%7}, {%8,%9}, {%0,%1,%2,%3};"
        : "+f"(c[0]), "+f"(c[1]), "+f"(c[2]), "+f"(c[3])
        : "r"(a[0]), "r"(a[1]), "r"(a[2]), "r"(a[3]), "r"(b[0]), "r"(b[1]));
}

// ---------------- kernels ----------------
// fp32 -> bf16 pre-conversion of x_user, x_item, and the 4 weight matrices
__global__ void convert_kernel(const float* __restrict__ xu, const float* __restrict__ xi,
                               const float* __restrict__ Wq, const float* __restrict__ Wk,
                               const float* __restrict__ Wv, const float* __restrict__ Wo) {
    int gid = blockIdx.x * blockDim.x + threadIdx.x;
    int T = gridDim.x * blockDim.x;
    const int NX = NN * C / 4;
    for (int i = gid; i < NX; i += T) {
        float4 a = *(const float4*)(xu + i * 4);
        float4 b = *(const float4*)(xi + i * 4);
        *(__nv_bfloat162*)(g_xb + i * 4)              = __float22bfloat162_rn(make_float2(a.x, a.y));
        *(__nv_bfloat162*)(g_xb + i * 4 + 2)          = __float22bfloat162_rn(make_float2(a.z, a.w));
        *(__nv_bfloat162*)(g_xb + NN * C + i * 4)     = __float22bfloat162_rn(make_float2(b.x, b.y));
        *(__nv_bfloat162*)(g_xb + NN * C + i * 4 + 2) = __float22bfloat162_rn(make_float2(b.z, b.w));
    }
    const int NW = C * C / 4;   // 4096
    for (int i = gid; i < NW; i += T) {
        const float* ws[4] = { Wq, Wk, Wv, Wo };
        #pragma unroll
        for (int w = 0; w < 4; w++) {
            float4 a = *(const float4*)(ws[w] + i * 4);
            *(__nv_bfloat162*)(g_wb + w * C * C + i * 4)     = __float22bfloat162_rn(make_float2(a.x, a.y));
            *(__nv_bfloat162*)(g_wb + w * C * C + i * 4 + 2) = __float22bfloat162_rn(make_float2(a.z, a.w));
        }
    }
}

__global__ void clear_kernel() {
    int gid = blockIdx.x * blockDim.x + threadIdx.x;
    int T = gridDim.x * blockDim.x;
    for (int i = gid; i < 4 * HSIZE; i += T) { g_ht_keys[i] = -1; g_ht_cnt[i] = 0; }
    for (int i = gid; i < NN; i += T) {
        g_cnt_su[i] = 0; g_cnt_du[i] = 0; g_cnt_si[i] = 0; g_cnt_di[i] = 0;
        g_cur0[i] = 0; g_cur1[i] = 0;
    }
}

__global__ void build_ht_kernel(const int* __restrict__ eui, const int* __restrict__ eiu) {
    int e = blockIdx.x * blockDim.x + threadIdx.x;
    if (e >= 2 * E) return;
    if (e < E) {
        int su = eui[e], du = eui[e + E];
        ht_insert(0, su * NI + du);      // pid_ui multiset
        ht_insert(3, du * NU + su);      // rev pairs for iu relation
        atomicAdd(&g_cnt_su[su], 1);
        atomicAdd(&g_cnt_du[du], 1);
    } else {
        int i = e - E;
        int si = eiu[i], di = eiu[i + E];
        ht_insert(1, si * NU + di);      // pid_iu multiset
        ht_insert(2, di * NI + si);      // rev pairs for ui relation
        atomicAdd(&g_cnt_si[si], 1);
        atomicAdd(&g_cnt_di[di], 1);
    }
}

// exclusive prefix scan of per-dst degree -> CSR offsets. one block per relation.
__global__ __launch_bounds__(1024) void scan_kernel() {
    int which = blockIdx.x;
    const int* cnt = which ? g_cnt_di : g_cnt_du;
    int* off = which ? g_off1 : g_off0;
    __shared__ int wsum[32];
    __shared__ int carry;
    int tid = threadIdx.x, lane = tid & 31, wid = tid >> 5;
    if (tid == 0) carry = 0;
    __syncthreads();
    for (int base = 0; base < NN; base += 1024) {
        int i = base + tid;
        int v = (i < NN) ? cnt[i] : 0;
        int x = v;
        #pragma unroll
        for (int d = 1; d < 32; d <<= 1) {
            int y = __shfl_up_sync(0xffffffffu, x, d);
            if (lane >= d) x += y;
        }
        if (lane == 31) wsum[wid] = x;
        __syncthreads();
        if (wid == 0) {
            int s = wsum[lane];
            #pragma unroll
            for (int d = 1; d < 32; d <<= 1) {
                int y = __shfl_up_sync(0xffffffffu, s, d);
                if (lane >= d) s += y;
            }
            wsum[lane] = s;   // inclusive across warps
        }
        __syncthreads();
        int wprefix = (wid == 0) ? 0 : wsum[wid - 1];
        int excl = carry + wprefix + (x - v);
        if (i < NN) off[i] = excl;
        __syncthreads();
        if (tid == 0) carry += wsum[31];
        __syncthreads();
    }
}

// scatter edges into CSR order + precompute per-edge head bias float4
__global__ void scatter_kernel(const int* __restrict__ eui, const int* __restrict__ eiu,
                               const float* __restrict__ t_user, const float* __restrict__ t_item,
                               const float* __restrict__ hb, const float* __restrict__ beta,
                               const float* __restrict__ tau_raw,
                               const float* __restrict__ gamma, const float* __restrict__ delta) {
    int idx = blockIdx.x * blockDim.x + threadIdx.x;
    if (idx >= 2 * E) return;
    int r = (idx >= E) ? 1 : 0;
    int e = idx - r * E;
    const int* ei = r ? eiu : eui;
    int src = ei[e], dst = ei[e + E];
    int* cur = r ? g_cur1 : g_cur0;
    const int* off = r ? g_off1 : g_off0;
    int pos = off[dst] + atomicAdd(&cur[dst], 1);
    g_src_s[r * E + pos] = src;

    float ts = (r ? t_item : t_user)[src];
    float td = (r ? t_user : t_item)[dst];
    float dt = fabsf(td - ts) + 1e-6f;
    int pid = src * 40000 + dst;
    float cntf = (float)(ht_query(r, pid) - 1);
    float recf = (ht_query(2 + r, pid) > 0) ? 1.f : 0.f;
    float tau = log1pf(expf(tau_raw[r])) + 1e-6f;
    float a = -log1pf(dt / tau);
    float b = log1pf(cntf);
    float4 bias;
    bias.x = hb[r * H + 0] + a * beta[r * H + 0] + b * gamma[r * H + 0] + recf * delta[r * H + 0];
    bias.y = hb[r * H + 1] + a * beta[r * H + 1] + b * gamma[r * H + 1] + recf * delta[r * H + 1];
    bias.z = hb[r * H + 2] + a * beta[r * H + 2] + b * gamma[r * H + 2] + recf * delta[r * H + 2];
    bias.w = hb[r * H + 3] + a * beta[r * H + 3] + b * gamma[r * H + 3] + recf * delta[r * H + 3];
    g_bias4[r * E + pos] = bias;
}

// fused edge attention: warp per destination, online softmax + weighted-V accumulate.
// (R8 single-edge loop; writes aggregate as bf16.)
__global__ __launch_bounds__(256) void attn_kernel() {
    int n = (blockIdx.x * blockDim.x + threadIdx.x) >> 5;
    int lane = threadIdx.x & 31;
    int r = blockIdx.y;
    if (n >= NN) return;

    const float* Q     = g_proj + (size_t)(r == 0 ? 3 : 0) * NN * C + (size_t)n * C;
    const float* Kbase = g_proj + (size_t)(r == 0 ? 1 : 4) * NN * C;
    const float* Vbase = g_proj + (size_t)(r == 0 ? 2 : 5) * NN * C;
    const int* off = r ? g_off1 : g_off0;
    int s0 = off[n];
    int s1 = (n + 1 < NN) ? off[n + 1] : E;
    const int* srcs = g_src_s + r * E;
    const float4* bias = g_bias4 + r * E;

    float4 q = *(const float4*)(Q + lane * 4);
    int h = lane >> 3;

    float m = -INFINITY, z = 0.f;
    float a0 = 0.f, a1 = 0.f, a2 = 0.f, a3 = 0.f;

    for (int j = s0; j < s1; j++) {
        int src = srcs[j];
        const float4 k = *(const float4*)(Kbase + (size_t)src * C + lane * 4);
        float p = q.x * k.x + q.y * k.y + q.z * k.z + q.w * k.w;
        p += __shfl_xor_sync(0xffffffffu, p, 1);
        p += __shfl_xor_sync(0xffffffffu, p, 2);
        p += __shfl_xor_sync(0xffffffffu, p, 4);   // 8-lane group = this head's dot

        float4 b4 = bias[j];
        float bh = (h == 0) ? b4.x : (h == 1) ? b4.y : (h == 2) ? b4.z : b4.w;
        float s = p * 0.1767766952966369f + bh;

        float mn = fmaxf(m, s);
        float fac = __expf(m - mn);     // first iter: exp(-inf) = 0
        float es  = __expf(s - mn);
        z = z * fac + es;
        const float4 v = *(const float4*)(Vbase + (size_t)src * C + lane * 4);
        a0 = a0 * fac + es * v.x;
        a1 = a1 * fac + es * v.y;
        a2 = a2 * fac + es * v.z;
        a3 = a3 * fac + es * v.w;
        m = mn;
    }

    float inv = (z > 0.f) ? 1.f / z : 0.f;
    __nv_bfloat16* ag = g_aggb + (size_t)r * NN * C + (size_t)n * C + lane * 4;
    *(__nv_bfloat162*)(ag)     = __float22bfloat162_rn(make_float2(a0 * inv, a1 * inv));
    *(__nv_bfloat162*)(ag + 2) = __float22bfloat162_rn(make_float2(a2 * inv, a3 * inv));
}

// ------------- bf16 tensor-core GEMM (bf16 inputs): C = A @ W^T (+bias) -------------
struct GemmJobB { const __nv_bfloat16* A; const __nv_bfloat16* W; const float* bias; float* out; };
struct GemmJobsB6 { GemmJobB j[6]; };

#define BSM_STRIDE 136   // bf16 elems per row: 17 x 16B -> ldmatrix conflict-free
#define BSM_BYTES (2 * 128 * BSM_STRIDE * 2)   // 69632 B

// shared tile loader: global bf16 [rows][128] -> smem [128][136]
__device__ __forceinline__ void load_tile_bf16(__nv_bfloat16* dstA, const __nv_bfloat16* A,
                                               __nv_bfloat16* dstW, const __nv_bfloat16* W,
                                               int tid) {
    #pragma unroll 4
    for (int i = tid; i < 128 * 16; i += 256) {
        int r = i >> 4, c8 = (i & 15) << 3;
        *(uint4*)(dstA + r * BSM_STRIDE + c8) = *(const uint4*)(A + r * 128 + c8);
        *(uint4*)(dstW + r * BSM_STRIDE + c8) = *(const uint4*)(W + r * 128 + c8);
    }
}

// core 128x128x128 compute from smem tiles
__device__ __forceinline__ void gemm_core(const __nv_bfloat16* As, const __nv_bfloat16* Ws,
                                          int warp, int lane, float acc[2][8][4]) {
    int wm = warp >> 1, wn = warp & 1;
    uint32_t sA = (uint32_t)__cvta_generic_to_shared(As);
    uint32_t sW = (uint32_t)__cvta_generic_to_shared(Ws);
    uint32_t aAddr[2], bAddr[4];
    #pragma unroll
    for (int mt = 0; mt < 2; mt++) {
        int row = wm * 32 + mt * 16 + (lane & 15);
        int col = (lane >> 4) << 3;
        aAddr[mt] = sA + (row * BSM_STRIDE + col) * 2;
    }
    #pragma unroll
    for (int ntp = 0; ntp < 4; ntp++) {
        int row = wn * 64 + ntp * 16 + ((lane >> 4) << 3) + (lane & 7);
        int col = ((lane >> 3) & 1) << 3;
        bAddr[ntp] = sW + (row * BSM_STRIDE + col) * 2;
    }
    #pragma unroll
    for (int ks = 0; ks < 8; ks++) {
        uint32_t koff = ks * 32;
        uint32_t a[2][4], b[8][2];
        ldsm4(a[0][0], a[0][1], a[0][2], a[0][3], aAddr[0] + koff);
        ldsm4(a[1][0], a[1][1], a[1][2], a[1][3], aAddr[1] + koff);
        #pragma unroll
        for (int ntp = 0; ntp < 4; ntp++)
            ldsm4(b[2 * ntp][0], b[2 * ntp][1], b[2 * ntp + 1][0], b[2 * ntp + 1][1],
                  bAddr[ntp] + koff);
        #pragma unroll
        for (int mt = 0; mt < 2; mt++)
            #pragma unroll
            for (int nt = 0; nt < 8; nt++)
                mma_bf16(acc[mt][nt], a[mt], b[nt]);
    }
}

__global__ __launch_bounds__(256) void gemm_bf16_kernel(GemmJobsB6 jobs, int M) {
    const GemmJobB jb = jobs.j[blockIdx.y];
    extern __shared__ __nv_bfloat16 shb[];
    __nv_bfloat16* As = shb;
    __nv_bfloat16* Ws = shb + 128 * BSM_STRIDE;
    int tid = threadIdx.x;
    int row0 = blockIdx.x * 128;

    load_tile_bf16(As, jb.A + (size_t)row0 * 128, Ws, jb.W, tid);
    __syncthreads();

    int warp = tid >> 5, lane = tid & 31;
    int wm = warp >> 1, wn = warp & 1;
    int g = lane >> 2, t4 = lane & 3;

    float acc[2][8][4];
    #pragma unroll
    for (int mt = 0; mt < 2; mt++)
        #pragma unroll
        for (int nt = 0; nt < 8; nt++)
            #pragma unroll
            for (int q = 0; q < 4; q++) acc[mt][nt][q] = 0.f;

    gemm_core(As, Ws, warp, lane, acc);

    #pragma unroll
    for (int mt = 0; mt < 2; mt++) {
        #pragma unroll
        for (int half = 0; half < 2; half++) {
            int row = row0 + wm * 32 + mt * 16 + g + half * 8;
            if (row >= M) continue;
            float* orow = jb.out + (size_t)row * 128 + wn * 64;
            #pragma unroll
            for (int nt = 0; nt < 8; nt++) {
                int col = nt * 8 + t4 * 2;
                float b0 = 0.f, b1 = 0.f;
                if (jb.bias) {
                    b0 = jb.bias[wn * 64 + col];
                    b1 = jb.bias[wn * 64 + col + 1];
                }
                float2 o = make_float2(acc[mt][nt][half * 2 + 0] + b0,
                                       acc[mt][nt][half * 2 + 1] + b1);
                *(float2*)(orow + col) = o;
            }
        }
    }
}

// final: out = LayerNorm(proj + indeg*bo + deg + x). one warp per node.
__global__ void final_kernel(const float* __restrict__ x_user, const float* __restrict__ x_item,
                             const float* __restrict__ bo, float* __restrict__ out) {
    int n = (blockIdx.x * blockDim.x + threadIdx.x) >> 5;
    int lane = threadIdx.x & 31;
    int ty = blockIdx.y;     // 0 = user, 1 = item
    if (n >= NN) return;
    float* o = out + (ty == 0 ? (size_t)0 : (size_t)NN * C) + (size_t)n * C;
    const float* x = (ty == 0 ? x_user : x_item) + (size_t)n * C;
    float indeg = (float)(ty == 0 ? g_cnt_di[n] : g_cnt_du[n]);
    float deg = (float)(ty == 0 ? (g_cnt_su[n] + g_cnt_di[n])
                                : (g_cnt_du[n] + g_cnt_si[n]));
    float4 v  = *(float4*)(o + lane * 4);
    float4 xv = *(const float4*)(x + lane * 4);
    float4 bv = *(const float4*)(bo + lane * 4);
    v.x += xv.x + indeg * bv.x + deg;
    v.y += xv.y + indeg * bv.y + deg;
    v.z += xv.z + indeg * bv.z + deg;
    v.w += xv.w + indeg * bv.w + deg;
    float s = v.x + v.y + v.z + v.w;
    #pragma unroll
    for (int d = 16; d; d >>= 1) s += __shfl_xor_sync(0xffffffffu, s, d);
    float mu = s * (1.f / 128.f);
    float d0 = v.x - mu, d1 = v.y - mu, d2 = v.z - mu, d3 = v.w - mu;
    float q = d0 * d0 + d1 * d1 + d2 * d2 + d3 * d3;
    #pragma unroll
    for (int d = 16; d; d >>= 1) q += __shfl_xor_sync(0xffffffffu, q, d);
    float inv = 1.f / sqrtf(q * (1.f / 128.f) + 1e-5f);
    float4 r4 = make_float4(d0 * inv, d1 * inv, d2 * inv, d3 * inv);
    *(float4*)(o + lane * 4) = r4;
}

// ---------------- launch ----------------
extern "C" void kernel_launch(void* const* d_in, const int* in_sizes, int n_in,
                              void* d_out, int out_size) {
    const float* x_user  = (const float*)d_in[0];
    const float* x_item  = (const float*)d_in[1];
    const float* t_user  = (const float*)d_in[2];
    const float* t_item  = (const float*)d_in[3];
    const int*   eui     = (const int*)d_in[4];
    const int*   eiu     = (const int*)d_in[5];
    const float* Wq      = (const float*)d_in[6];
    const float* bq      = (const float*)d_in[7];
    const float* Wk      = (const float*)d_in[8];
    const float* bk      = (const float*)d_in[9];
    const float* Wv      = (const float*)d_in[10];
    const float* bv      = (const float*)d_in[11];
    const float* Wo      = (const float*)d_in[12];
    const float* bo      = (const float*)d_in[13];
    const float* hb      = (const float*)d_in[14];
    const float* beta    = (const float*)d_in[15];
    const float* tau_raw = (const float*)d_in[16];
    const float* gammaP  = (const float*)d_in[17];
    const float* deltaP  = (const float*)d_in[18];
    float* out = (float*)d_out;

    float* proj;
    __nv_bfloat16 *xb, *wb, *aggb;
    cudaGetSymbolAddress((void**)&proj, g_proj);
    cudaGetSymbolAddress((void**)&xb, g_xb);
    cudaGetSymbolAddress((void**)&wb, g_wb);
    cudaGetSymbolAddress((void**)&aggb, g_aggb);

    cudaFuncSetAttribute(gemm_bf16_kernel,
                         cudaFuncAttributeMaxDynamicSharedMemorySize, BSM_BYTES);

    // 1: convert  2: clear  3: build_ht  4: QKV gemm (profiled)  5: scan
    // 6: scatter  7: attn   8: O gemm  9: final
    convert_kernel<<<512, 256>>>(x_user, x_item, Wq, Wk, Wv, Wo);
    clear_kernel<<<512, 256>>>();
    build_ht_kernel<<<(2 * E + 255) / 256, 256>>>(eui, eiu);

    int gblocks = (NN + 127) / 128;   // 313

    GemmJobsB6 qkv;
    qkv.j[0] = { xb,          wb,             bq, proj + (size_t)0 * NN * C };
    qkv.j[1] = { xb,          wb + C * C,     bk, proj + (size_t)1 * NN * C };
    qkv.j[2] = { xb,          wb + 2 * C * C, bv, proj + (size_t)2 * NN * C };
    qkv.j[3] = { xb + NN * C, wb,             bq, proj + (size_t)3 * NN * C };
    qkv.j[4] = { xb + NN * C, wb + C * C,     bk, proj + (size_t)4 * NN * C };
    qkv.j[5] = { xb + NN * C, wb + 2 * C * C, bv, proj + (size_t)5 * NN * C };
    gemm_bf16_kernel<<<dim3(gblocks, 6), 256, BSM_BYTES>>>(qkv, NN);

    scan_kernel<<<2, 1024>>>();
    scatter_kernel<<<(2 * E + 255) / 256, 256>>>(eui, eiu, t_user, t_item,
                                                 hb, beta, tau_raw, gammaP, deltaP);

    dim3 agrid((NN * 32 + 255) / 256, 2);
    attn_kernel<<<agrid, 256>>>();

    // relation 0 (user->item) feeds out_item; relation 1 feeds out_user
    GemmJobsB6 ojobs;
    ojobs.j[0] = { aggb,          wb + 3 * C * C, nullptr, out + (size_t)NN * C };
    ojobs.j[1] = { aggb + NN * C, wb + 3 * C * C, nullptr, out };
    ojobs.j[2] = ojobs.j[0]; ojobs.j[3] = ojobs.j[0];
    ojobs.j[4] = ojobs.j[0]; ojobs.j[5] = ojobs.j[0];
    gemm_bf16_kernel<<<dim3(gblocks, 2), 256, BSM_BYTES>>>(ojobs, NN);

    dim3 fgrid((NN * 32 + 255) / 256, 2);
    final_kernel<<<fgrid, 256>>>(x_user, x_item, bo, out);
}

// round 14
// speedup vs baseline: 1.2153x; 1.0001x over previous
#include <cuda_runtime.h>
#include <cuda_bf16.h>
#include <cstdint>
#include <math.h>

#define NU 40000
#define NI 40000
#define NN 40000
#define C 128
#define H 4
#define HD 32
#define E 200000
#define HSIZE (1 << 19)
#define HMASK (HSIZE - 1)

// ---------------- device scratch (static, no allocs) ----------------
__device__ int   g_ht_keys[4 * HSIZE];
__device__ int   g_ht_cnt [4 * HSIZE];
__device__ float g_proj[6 * NN * C];        // 0:Qu 1:Ku 2:Vu 3:Qi 4:Ki 5:Vi (fp32)
__device__ __nv_bfloat16 g_xb [2 * NN * C + 64 * C];   // bf16 x_user | x_item (+pad)
__device__ __nv_bfloat16 g_wb [4 * C * C];             // bf16 Wq Wk Wv Wo
__device__ __nv_bfloat16 g_aggb[2 * NN * C + 64 * C];  // bf16 attn aggregate (+pad)
__device__ int g_cnt_su[NN], g_cnt_du[NN], g_cnt_si[NN], g_cnt_di[NN];
__device__ int g_off0[NN], g_off1[NN];   // CSR offsets (rel0 dst=item, rel1 dst=user)
__device__ int g_cur0[NN], g_cur1[NN];   // scatter cursors
__device__ int    g_src_s[2 * E];        // CSR-sorted source ids
__device__ float4 g_bias4[2 * E];        // per-edge per-head score bias (precomputed)

// ---------------- helpers ----------------
__device__ __forceinline__ unsigned hash_key(int key) {
    unsigned h = (unsigned)key * 2654435761u;
    h ^= h >> 15;
    return h & HMASK;
}

__device__ __forceinline__ void ht_insert(int t, int key) {
    unsigned slot = hash_key(key);
    int* keys = g_ht_keys + t * HSIZE;
    int* cnts = g_ht_cnt + t * HSIZE;
    while (true) {
        int k = keys[slot];
        if (k == key) { atomicAdd(&cnts[slot], 1); return; }
        if (k == -1) {
            int old = atomicCAS(&keys[slot], -1, key);
            if (old == -1 || old == key) { atomicAdd(&cnts[slot], 1); return; }
        }
        slot = (slot + 1) & HMASK;
    }
}

__device__ __forceinline__ int ht_query(int t, int key) {
    unsigned slot = hash_key(key);
    const int* keys = g_ht_keys + t * HSIZE;
    const int* cnts = g_ht_cnt + t * HSIZE;
    while (true) {
        int k = keys[slot];
        if (k == key) return cnts[slot];
        if (k == -1) return 0;
        slot = (slot + 1) & HMASK;
    }
}

__device__ __forceinline__ void ldsm4(uint32_t& r0, uint32_t& r1, uint32_t& r2, uint32_t& r3,
                                      uint32_t addr) {
    asm volatile("ldmatrix.sync.aligned.m8n8.x4.shared.b16 {%0,%1,%2,%3}, [%4];"
                 : "=r"(r0), "=r"(r1), "=r"(r2), "=r"(r3) : "r"(addr));
}

__device__ __forceinline__ void mma_bf16(float* c, const uint32_t* a, const uint32_t* b) {
    asm volatile(
        "mma.sync.aligned.m16n8k16.row.col.f32.bf16.bf16.f32 "
        "{%0,%1,%2,%3}, {%4,%5,%6,%7}, {%8,%9}, {%0,%1,%2,%3};"
        : "+f"(c[0]), "+f"(c[1]), "+f"(c[2]), "+f"(c[3])
        : "r"(a[0]), "r"(a[1]), "r"(a[2]), "r"(a[3]), "r"(b[0]), "r"(b[1]));
}

// ---------------- kernels ----------------
// fused: fp32->bf16 pre-conversion + scratch clearing
__global__ void convert_clear_kernel(const float* __restrict__ xu, const float* __restrict__ xi,
                                     const float* __restrict__ Wq, const float* __restrict__ Wk,
                                     const float* __restrict__ Wv, const float* __restrict__ Wo) {
    int gid = blockIdx.x * blockDim.x + threadIdx.x;
    int T = gridDim.x * blockDim.x;
    const int NX = NN * C / 4;
    for (int i = gid; i < NX; i += T) {
        float4 a = *(const float4*)(xu + i * 4);
        float4 b = *(const float4*)(xi + i * 4);
        *(__nv_bfloat162*)(g_xb + i * 4)              = __float22bfloat162_rn(make_float2(a.x, a.y));
        *(__nv_bfloat162*)(g_xb + i * 4 + 2)          = __float22bfloat162_rn(make_float2(a.z, a.w));
        *(__nv_bfloat162*)(g_xb + NN * C + i * 4)     = __float22bfloat162_rn(make_float2(b.x, b.y));
        *(__nv_bfloat162*)(g_xb + NN * C + i * 4 + 2) = __float22bfloat162_rn(make_float2(b.z, b.w));
    }
    const int NW = C * C / 4;   // 4096
    for (int i = gid; i < NW; i += T) {
        const float* ws[4] = { Wq, Wk, Wv, Wo };
        #pragma unroll
        for (int w = 0; w < 4; w++) {
            float4 a = *(const float4*)(ws[w] + i * 4);
            *(__nv_bfloat162*)(g_wb + w * C * C + i * 4)     = __float22bfloat162_rn(make_float2(a.x, a.y));
            *(__nv_bfloat162*)(g_wb + w * C * C + i * 4 + 2) = __float22bfloat162_rn(make_float2(a.z, a.w));
        }
    }
    for (int i = gid; i < 4 * HSIZE; i += T) { g_ht_keys[i] = -1; g_ht_cnt[i] = 0; }
    for (int i = gid; i < NN; i += T) {
        g_cnt_su[i] = 0; g_cnt_du[i] = 0; g_cnt_si[i] = 0; g_cnt_di[i] = 0;
        g_cur0[i] = 0; g_cur1[i] = 0;
    }
}

__global__ void build_ht_kernel(const int* __restrict__ eui, const int* __restrict__ eiu) {
    int e = blockIdx.x * blockDim.x + threadIdx.x;
    if (e >= 2 * E) return;
    if (e < E) {
        int su = eui[e], du = eui[e + E];
        ht_insert(0, su * NI + du);      // pid_ui multiset
        ht_insert(3, du * NU + su);      // rev pairs for iu relation
        atomicAdd(&g_cnt_su[su], 1);
        atomicAdd(&g_cnt_du[du], 1);
    } else {
        int i = e - E;
        int si = eiu[i], di = eiu[i + E];
        ht_insert(1, si * NU + di);      // pid_iu multiset
        ht_insert(2, di * NI + si);      // rev pairs for ui relation
        atomicAdd(&g_cnt_si[si], 1);
        atomicAdd(&g_cnt_di[di], 1);
    }
}

// exclusive prefix scan of per-dst degree -> CSR offsets. one block per relation.
__global__ __launch_bounds__(1024) void scan_kernel() {
    int which = blockIdx.x;
    const int* cnt = which ? g_cnt_di : g_cnt_du;
    int* off = which ? g_off1 : g_off0;
    __shared__ int wsum[32];
    __shared__ int carry;
    int tid = threadIdx.x, lane = tid & 31, wid = tid >> 5;
    if (tid == 0) carry = 0;
    __syncthreads();
    for (int base = 0; base < NN; base += 1024) {
        int i = base + tid;
        int v = (i < NN) ? cnt[i] : 0;
        int x = v;
        #pragma unroll
        for (int d = 1; d < 32; d <<= 1) {
            int y = __shfl_up_sync(0xffffffffu, x, d);
            if (lane >= d) x += y;
        }
        if (lane == 31) wsum[wid] = x;
        __syncthreads();
        if (wid == 0) {
            int s = wsum[lane];
            #pragma unroll
            for (int d = 1; d < 32; d <<= 1) {
                int y = __shfl_up_sync(0xffffffffu, s, d);
                if (lane >= d) s += y;
            }
            wsum[lane] = s;   // inclusive across warps
        }
        __syncthreads();
        int wprefix = (wid == 0) ? 0 : wsum[wid - 1];
        int excl = carry + wprefix + (x - v);
        if (i < NN) off[i] = excl;
        __syncthreads();
        if (tid == 0) carry += wsum[31];
        __syncthreads();
    }
}

// scatter edges into CSR order + precompute per-edge head bias float4
__global__ void scatter_kernel(const int* __restrict__ eui, const int* __restrict__ eiu,
                               const float* __restrict__ t_user, const float* __restrict__ t_item,
                               const float* __restrict__ hb, const float* __restrict__ beta,
                               const float* __restrict__ tau_raw,
                               const float* __restrict__ gamma, const float* __restrict__ delta) {
    int idx = blockIdx.x * blockDim.x + threadIdx.x;
    if (idx >= 2 * E) return;
    int r = (idx >= E) ? 1 : 0;
    int e = idx - r * E;
    const int* ei = r ? eiu : eui;
    int src = ei[e], dst = ei[e + E];
    int* cur = r ? g_cur1 : g_cur0;
    const int* off = r ? g_off1 : g_off0;
    int pos = off[dst] + atomicAdd(&cur[dst], 1);
    g_src_s[r * E + pos] = src;

    float ts = (r ? t_item : t_user)[src];
    float td = (r ? t_user : t_item)[dst];
    float dt = fabsf(td - ts) + 1e-6f;
    int pid = src * 40000 + dst;
    float cntf = (float)(ht_query(r, pid) - 1);
    float recf = (ht_query(2 + r, pid) > 0) ? 1.f : 0.f;
    float tau = log1pf(expf(tau_raw[r])) + 1e-6f;
    float a = -log1pf(dt / tau);
    float b = log1pf(cntf);
    float4 bias;
    bias.x = hb[r * H + 0] + a * beta[r * H + 0] + b * gamma[r * H + 0] + recf * delta[r * H + 0];
    bias.y = hb[r * H + 1] + a * beta[r * H + 1] + b * gamma[r * H + 1] + recf * delta[r * H + 1];
    bias.z = hb[r * H + 2] + a * beta[r * H + 2] + b * gamma[r * H + 2] + recf * delta[r * H + 2];
    bias.w = hb[r * H + 3] + a * beta[r * H + 3] + b * gamma[r * H + 3] + recf * delta[r * H + 3];
    g_bias4[r * E + pos] = bias;
}

// fused edge attention: warp per destination, online softmax + weighted-V accumulate.
__global__ __launch_bounds__(256) void attn_kernel() {
    int n = (blockIdx.x * blockDim.x + threadIdx.x) >> 5;
    int lane = threadIdx.x & 31;
    int r = blockIdx.y;
    if (n >= NN) return;

    const float* Q     = g_proj + (size_t)(r == 0 ? 3 : 0) * NN * C + (size_t)n * C;
    const float* Kbase = g_proj + (size_t)(r == 0 ? 1 : 4) * NN * C;
    const float* Vbase = g_proj + (size_t)(r == 0 ? 2 : 5) * NN * C;
    const int* off = r ? g_off1 : g_off0;
    int s0 = off[n];
    int s1 = (n + 1 < NN) ? off[n + 1] : E;
    const int* srcs = g_src_s + r * E;
    const float4* bias = g_bias4 + r * E;

    float4 q = *(const float4*)(Q + lane * 4);
    int h = lane >> 3;

    float m = -INFINITY, z = 0.f;
    float a0 = 0.f, a1 = 0.f, a2 = 0.f, a3 = 0.f;

    for (int j = s0; j < s1; j++) {
        int src = srcs[j];
        const float4 k = *(const float4*)(Kbase + (size_t)src * C + lane * 4);
        float p = q.x * k.x + q.y * k.y + q.z * k.z + q.w * k.w;
        p += __shfl_xor_sync(0xffffffffu, p, 1);
        p += __shfl_xor_sync(0xffffffffu, p, 2);
        p += __shfl_xor_sync(0xffffffffu, p, 4);   // 8-lane group = this head's dot

        float4 b4 = bias[j];
        float bh = (h == 0) ? b4.x : (h == 1) ? b4.y : (h == 2) ? b4.z : b4.w;
        float s = p * 0.1767766952966369f + bh;

        float mn = fmaxf(m, s);
        float fac = __expf(m - mn);     // first iter: exp(-inf) = 0
        float es  = __expf(s - mn);
        z = z * fac + es;
        const float4 v = *(const float4*)(Vbase + (size_t)src * C + lane * 4);
        a0 = a0 * fac + es * v.x;
        a1 = a1 * fac + es * v.y;
        a2 = a2 * fac + es * v.z;
        a3 = a3 * fac + es * v.w;
        m = mn;
    }

    float inv = (z > 0.f) ? 1.f / z : 0.f;
    __nv_bfloat16* ag = g_aggb + (size_t)r * NN * C + (size_t)n * C + lane * 4;
    *(__nv_bfloat162*)(ag)     = __float22bfloat162_rn(make_float2(a0 * inv, a1 * inv));
    *(__nv_bfloat162*)(ag + 2) = __float22bfloat162_rn(make_float2(a2 * inv, a3 * inv));
}

// ------------- bf16 tensor-core GEMM machinery -------------
#define BSM_STRIDE 136   // bf16 elems per row: 17 x 16B -> ldmatrix conflict-free
#define BSM_BYTES (2 * 128 * BSM_STRIDE * 2)   // 69632 B

// core 128x128x128 compute from smem tiles
__device__ __forceinline__ void gemm_core(const __nv_bfloat16* As, const __nv_bfloat16* Ws,
                                          int warp, int lane, float acc[2][8][4]) {
    int wm = warp >> 1, wn = warp & 1;
    uint32_t sA = (uint32_t)__cvta_generic_to_shared(As);
    uint32_t sW = (uint32_t)__cvta_generic_to_shared(Ws);
    uint32_t aAddr[2], bAddr[4];
    #pragma unroll
    for (int mt = 0; mt < 2; mt++) {
        int row = wm * 32 + mt * 16 + (lane & 15);
        int col = (lane >> 4) << 3;
        aAddr[mt] = sA + (row * BSM_STRIDE + col) * 2;
    }
    #pragma unroll
    for (int ntp = 0; ntp < 4; ntp++) {
        int row = wn * 64 + ntp * 16 + ((lane >> 4) << 3) + (lane & 7);
        int col = ((lane >> 3) & 1) << 3;
        bAddr[ntp] = sW + (row * BSM_STRIDE + col) * 2;
    }
    #pragma unroll
    for (int ks = 0; ks < 8; ks++) {
        uint32_t koff = ks * 32;
        uint32_t a[2][4], b[8][2];
        ldsm4(a[0][0], a[0][1], a[0][2], a[0][3], aAddr[0] + koff);
        ldsm4(a[1][0], a[1][1], a[1][2], a[1][3], aAddr[1] + koff);
        #pragma unroll
        for (int ntp = 0; ntp < 4; ntp++)
            ldsm4(b[2 * ntp][0], b[2 * ntp][1], b[2 * ntp + 1][0], b[2 * ntp + 1][1],
                  bAddr[ntp] + koff);
        #pragma unroll
        for (int mt = 0; mt < 2; mt++)
            #pragma unroll
            for (int nt = 0; nt < 8; nt++)
                mma_bf16(acc[mt][nt], a[mt], b[nt]);
    }
}

// QKV GEMM: one block per (row-tile, relation); A loaded once, loop over Wq/Wk/Wv.
__global__ __launch_bounds__(256) void qkv_gemm_kernel(const float* __restrict__ bq,
                                                       const float* __restrict__ bk,
                                                       const float* __restrict__ bv) {
    int rel = blockIdx.y;
    extern __shared__ __nv_bfloat16 shb[];
    __nv_bfloat16* As = shb;
    __nv_bfloat16* Ws = shb + 128 * BSM_STRIDE;
    int tid = threadIdx.x;
    int row0 = blockIdx.x * 128;
    const __nv_bfloat16* A = g_xb + (size_t)rel * NN * C + (size_t)row0 * 128;

    // A tile -> smem (rows beyond NN read zero-padding in g_xb)
    #pragma unroll 4
    for (int i = tid; i < 128 * 16; i += 256) {
        int r = i >> 4, c8 = (i & 15) << 3;
        *(uint4*)(As + r * BSM_STRIDE + c8) = *(const uint4*)(A + r * 128 + c8);
    }

    int warp = tid >> 5, lane = tid & 31;
    int wm = warp >> 1, wn = warp & 1;
    int g = lane >> 2, t4 = lane & 3;
    const float* biases[3] = { bq, bk, bv };

    for (int j = 0; j < 3; j++) {
        if (j > 0) __syncthreads();   // prior job's ldsm reads done before Ws overwrite
        const __nv_bfloat16* W = g_wb + j * C * C;
        #pragma unroll 4
        for (int i = tid; i < 128 * 16; i += 256) {
            int r = i >> 4, c8 = (i & 15) << 3;
            *(uint4*)(Ws + r * BSM_STRIDE + c8) = *(const uint4*)(W + r * 128 + c8);
        }
        __syncthreads();

        float acc[2][8][4];
        #pragma unroll
        for (int mt = 0; mt < 2; mt++)
            #pragma unroll
            for (int nt = 0; nt < 8; nt++)
                #pragma unroll
                for (int q = 0; q < 4; q++) acc[mt][nt][q] = 0.f;

        gemm_core(As, Ws, warp, lane, acc);

        float* outb = g_proj + (size_t)(rel * 3 + j) * NN * C;
        const float* bias = biases[j];
        #pragma unroll
        for (int mt = 0; mt < 2; mt++) {
            #pragma unroll
            for (int half = 0; half < 2; half++) {
                int row = row0 + wm * 32 + mt * 16 + g + half * 8;
                if (row >= NN) continue;
                float* orow = outb + (size_t)row * 128 + wn * 64;
                #pragma unroll
                for (int nt = 0; nt < 8; nt++) {
                    int col = nt * 8 + t4 * 2;
                    float2 o = make_float2(acc[mt][nt][half * 2 + 0] + bias[wn * 64 + col],
                                           acc[mt][nt][half * 2 + 1] + bias[wn * 64 + col + 1]);
                    *(float2*)(orow + col) = o;
                }
            }
        }
    }
}

// O-projection GEMM: blockIdx.y = relation (0: agg0 -> out_item, 1: agg1 -> out_user)
__global__ __launch_bounds__(256) void ogemm_kernel(float* __restrict__ out) {
    int rel = blockIdx.y;
    extern __shared__ __nv_bfloat16 shb[];
    __nv_bfloat16* As = shb;
    __nv_bfloat16* Ws = shb + 128 * BSM_STRIDE;
    int tid = threadIdx.x;
    int row0 = blockIdx.x * 128;
    const __nv_bfloat16* A = g_aggb + (size_t)rel * NN * C + (size_t)row0 * 128;
    const __nv_bfloat16* W = g_wb + 3 * C * C;

    #pragma unroll 4
    for (int i = tid; i < 128 * 16; i += 256) {
        int r = i >> 4, c8 = (i & 15) << 3;
        *(uint4*)(As + r * BSM_STRIDE + c8) = *(const uint4*)(A + r * 128 + c8);
        *(uint4*)(Ws + r * BSM_STRIDE + c8) = *(const uint4*)(W + r * 128 + c8);
    }
    __syncthreads();

    int warp = tid >> 5, lane = tid & 31;
    int wm = warp >> 1, wn = warp & 1;
    int g = lane >> 2, t4 = lane & 3;

    float acc[2][8][4];
    #pragma unroll
    for (int mt = 0; mt < 2; mt++)
        #pragma unroll
        for (int nt = 0; nt < 8; nt++)
            #pragma unroll
            for (int q = 0; q < 4; q++) acc[mt][nt][q] = 0.f;

    gemm_core(As, Ws, warp, lane, acc);

    float* obase = out + (rel == 0 ? (size_t)NN * C : 0);
    #pragma unroll
    for (int mt = 0; mt < 2; mt++) {
        #pragma unroll
        for (int half = 0; half < 2; half++) {
            int row = row0 + wm * 32 + mt * 16 + g + half * 8;
            if (row >= NN) continue;
            float* orow = obase + (size_t)row * 128 + wn * 64;
            #pragma unroll
            for (int nt = 0; nt < 8; nt++) {
                int col = nt * 8 + t4 * 2;
                *(float2*)(orow + col) = make_float2(acc[mt][nt][half * 2 + 0],
                                                     acc[mt][nt][half * 2 + 1]);
            }
        }
    }
}

// final: out = LayerNorm(proj + indeg*bo + deg + x). one warp per node.
__global__ void final_kernel(const float* __restrict__ x_user, const float* __restrict__ x_item,
                             const float* __restrict__ bo, float* __restrict__ out) {
    int n = (blockIdx.x * blockDim.x + threadIdx.x) >> 5;
    int lane = threadIdx.x & 31;
    int ty = blockIdx.y;     // 0 = user, 1 = item
    if (n >= NN) return;
    float* o = out + (ty == 0 ? (size_t)0 : (size_t)NN * C) + (size_t)n * C;
    const float* x = (ty == 0 ? x_user : x_item) + (size_t)n * C;
    float indeg = (float)(ty == 0 ? g_cnt_di[n] : g_cnt_du[n]);
    float deg = (float)(ty == 0 ? (g_cnt_su[n] + g_cnt_di[n])
                                : (g_cnt_du[n] + g_cnt_si[n]));
    float4 v  = *(float4*)(o + lane * 4);
    float4 xv = *(const float4*)(x + lane * 4);
    float4 bv = *(const float4*)(bo + lane * 4);
    v.x += xv.x + indeg * bv.x + deg;
    v.y += xv.y + indeg * bv.y + deg;
    v.z += xv.z + indeg * bv.z + deg;
    v.w += xv.w + indeg * bv.w + deg;
    float s = v.x + v.y + v.z + v.w;
    #pragma unroll
    for (int d = 16; d; d >>= 1) s += __shfl_xor_sync(0xffffffffu, s, d);
    float mu = s * (1.f / 128.f);
    float d0 = v.x - mu, d1 = v.y - mu, d2 = v.z - mu, d3 = v.w - mu;
    float q = d0 * d0 + d1 * d1 + d2 * d2 + d3 * d3;
    #pragma unroll
    for (int d = 16; d; d >>= 1) q += __shfl_xor_sync(0xffffffffu, q, d);
    float inv = 1.f / sqrtf(q * (1.f / 128.f) + 1e-5f);
    float4 r4 = make_float4(d0 * inv, d1 * inv, d2 * inv, d3 * inv);
    *(float4*)(o + lane * 4) = r4;
}

// ---------------- launch ----------------
extern "C" void kernel_launch(void* const* d_in, const int* in_sizes, int n_in,
                              void* d_out, int out_size) {
    const float* x_user  = (const float*)d_in[0];
    const float* x_item  = (const float*)d_in[1];
    const float* t_user  = (const float*)d_in[2];
    const float* t_item  = (const float*)d_in[3];
    const int*   eui     = (const int*)d_in[4];
    const int*   eiu     = (const int*)d_in[5];
    const float* Wq      = (const float*)d_in[6];
    const float* bq      = (const float*)d_in[7];
    const float* Wk      = (const float*)d_in[8];
    const float* bk      = (const float*)d_in[9];
    const float* Wv      = (const float*)d_in[10];
    const float* bv      = (const float*)d_in[11];
    const float* Wo      = (const float*)d_in[12];
    const float* bo      = (const float*)d_in[13];
    const float* hb      = (const float*)d_in[14];
    const float* beta    = (const float*)d_in[15];
    const float* tau_raw = (const float*)d_in[16];
    const float* gammaP  = (const float*)d_in[17];
    const float* deltaP  = (const float*)d_in[18];
    float* out = (float*)d_out;

    cudaFuncSetAttribute(qkv_gemm_kernel,
                         cudaFuncAttributeMaxDynamicSharedMemorySize, BSM_BYTES);
    cudaFuncSetAttribute(ogemm_kernel,
                         cudaFuncAttributeMaxDynamicSharedMemorySize, BSM_BYTES);

    int gblocks = (NN + 127) / 128;   // 313

    // 1: convert+clear  2: build_ht  3: scan  4: QKV gemm (profiled)
    // 5: scatter  6: attn  7: O gemm  8: final
    convert_clear_kernel<<<512, 256>>>(x_user, x_item, Wq, Wk, Wv, Wo);
    build_ht_kernel<<<(2 * E + 255) / 256, 256>>>(eui, eiu);
    scan_kernel<<<2, 1024>>>();

    qkv_gemm_kernel<<<dim3(gblocks, 2), 256, BSM_BYTES>>>(bq, bk, bv);

    scatter_kernel<<<(2 * E + 255) / 256, 256>>>(eui, eiu, t_user, t_item,
                                                 hb, beta, tau_raw, gammaP, deltaP);

    dim3 agrid((NN * 32 + 255) / 256, 2);
    attn_kernel<<<agrid, 256>>>();

    ogemm_kernel<<<dim3(gblocks, 2), 256, BSM_BYTES>>>(out);

    dim3 fgrid((NN * 32 + 255) / 256, 2);
    final_kernel<<<fgrid, 256>>>(x_user, x_item, bo, out);
}

// round 16
// speedup vs baseline: 1.2276x; 1.0101x over previous
#include <cuda_runtime.h>
#include <cuda_bf16.h>
#include <cstdint>
#include <math.h>

#define NU 40000
#define NI 40000
#define NN 40000
#define C 128
#define H 4
#define HD 32
#define E 200000
#define HSIZE (1 << 19)
#define HMASK (HSIZE - 1)

// ---------------- device scratch (static, no allocs) ----------------
__device__ int   g_ht_keys[4 * HSIZE];
__device__ int   g_ht_cnt [4 * HSIZE];
__device__ float g_proj[6 * NN * C];        // 0:Qu 1:Ku 2:Vu 3:Qi 4:Ki 5:Vi (fp32)
__device__ __nv_bfloat16 g_xb [2 * NN * C + 64 * C];   // bf16 x_user | x_item (+pad)
__device__ __nv_bfloat16 g_wb [4 * C * C];             // bf16 Wq Wk Wv Wo
__device__ __nv_bfloat16 g_aggb[2 * NN * C + 64 * C];  // bf16 attn aggregate (+pad)
__device__ int g_cnt_su[NN], g_cnt_du[NN], g_cnt_si[NN], g_cnt_di[NN];
__device__ int g_off0[NN], g_off1[NN];   // CSR offsets (rel0 dst=item, rel1 dst=user)
__device__ int g_cur0[NN], g_cur1[NN];   // scatter cursors
__device__ int    g_src_s[2 * E];        // CSR-sorted source ids
__device__ float4 g_bias4[2 * E];        // per-edge per-head score bias (precomputed)

// ---------------- helpers ----------------
__device__ __forceinline__ unsigned hash_key(int key) {
    unsigned h = (unsigned)key * 2654435761u;
    h ^= h >> 15;
    return h & HMASK;
}

__device__ __forceinline__ void ht_insert(int t, int key) {
    unsigned slot = hash_key(key);
    int* keys = g_ht_keys + t * HSIZE;
    int* cnts = g_ht_cnt + t * HSIZE;
    while (true) {
        int k = keys[slot];
        if (k == key) { atomicAdd(&cnts[slot], 1); return; }
        if (k == -1) {
            int old = atomicCAS(&keys[slot], -1, key);
            if (old == -1 || old == key) { atomicAdd(&cnts[slot], 1); return; }
        }
        slot = (slot + 1) & HMASK;
    }
}

__device__ __forceinline__ int ht_query(int t, int key) {
    unsigned slot = hash_key(key);
    const int* keys = g_ht_keys + t * HSIZE;
    const int* cnts = g_ht_cnt + t * HSIZE;
    while (true) {
        int k = keys[slot];
        if (k == key) return cnts[slot];
        if (k == -1) return 0;
        slot = (slot + 1) & HMASK;
    }
}

__device__ __forceinline__ void ldsm4(uint32_t& r0, uint32_t& r1, uint32_t& r2, uint32_t& r3,
                                      uint32_t addr) {
    asm volatile("ldmatrix.sync.aligned.m8n8.x4.shared.b16 {%0,%1,%2,%3}, [%4];"
                 : "=r"(r0), "=r"(r1), "=r"(r2), "=r"(r3) : "r"(addr));
}

__device__ __forceinline__ void mma_bf16(float* c, const uint32_t* a, const uint32_t* b) {
    asm volatile(
        "mma.sync.aligned.m16n8k16.row.col.f32.bf16.bf16.f32 "
        "{%0,%1,%2,%3}, {%4,%5,%6,%7}, {%8,%9}, {%0,%1,%2,%3};"
        : "+f"(c[0]), "+f"(c[1]), "+f"(c[2]), "+f"(c[3])
        : "r"(a[0]), "r"(a[1]), "r"(a[2]), "r"(a[3]), "r"(b[0]), "r"(b[1]));
}

// ---------------- kernels ----------------
// fused: fp32->bf16 pre-conversion + scratch clearing
__global__ void convert_clear_kernel(const float* __restrict__ xu, const float* __restrict__ xi,
                                     const float* __restrict__ Wq, const float* __restrict__ Wk,
                                     const float* __restrict__ Wv, const float* __restrict__ Wo) {
    int gid = blockIdx.x * blockDim.x + threadIdx.x;
    int T = gridDim.x * blockDim.x;
    const int NX = NN * C / 4;
    for (int i = gid; i < NX; i += T) {
        float4 a = *(const float4*)(xu + i * 4);
        float4 b = *(const float4*)(xi + i * 4);
        *(__nv_bfloat162*)(g_xb + i * 4)              = __float22bfloat162_rn(make_float2(a.x, a.y));
        *(__nv_bfloat162*)(g_xb + i * 4 + 2)          = __float22bfloat162_rn(make_float2(a.z, a.w));
        *(__nv_bfloat162*)(g_xb + NN * C + i * 4)     = __float22bfloat162_rn(make_float2(b.x, b.y));
        *(__nv_bfloat162*)(g_xb + NN * C + i * 4 + 2) = __float22bfloat162_rn(make_float2(b.z, b.w));
    }
    const int NW = C * C / 4;   // 4096
    for (int i = gid; i < NW; i += T) {
        const float* ws[4] = { Wq, Wk, Wv, Wo };
        #pragma unroll
        for (int w = 0; w < 4; w++) {
            float4 a = *(const float4*)(ws[w] + i * 4);
            *(__nv_bfloat162*)(g_wb + w * C * C + i * 4)     = __float22bfloat162_rn(make_float2(a.x, a.y));
            *(__nv_bfloat162*)(g_wb + w * C * C + i * 4 + 2) = __float22bfloat162_rn(make_float2(a.z, a.w));
        }
    }
    for (int i = gid; i < 4 * HSIZE; i += T) { g_ht_keys[i] = -1; g_ht_cnt[i] = 0; }
    for (int i = gid; i < NN; i += T) {
        g_cnt_su[i] = 0; g_cnt_du[i] = 0; g_cnt_si[i] = 0; g_cnt_di[i] = 0;
        g_cur0[i] = 0; g_cur1[i] = 0;
    }
}

__global__ void build_ht_kernel(const int* __restrict__ eui, const int* __restrict__ eiu) {
    int e = blockIdx.x * blockDim.x + threadIdx.x;
    if (e >= 2 * E) return;
    if (e < E) {
        int su = eui[e], du = eui[e + E];
        ht_insert(0, su * NI + du);      // pid_ui multiset
        ht_insert(3, du * NU + su);      // rev pairs for iu relation
        atomicAdd(&g_cnt_su[su], 1);
        atomicAdd(&g_cnt_du[du], 1);
    } else {
        int i = e - E;
        int si = eiu[i], di = eiu[i + E];
        ht_insert(1, si * NU + di);      // pid_iu multiset
        ht_insert(2, di * NI + si);      // rev pairs for ui relation
        atomicAdd(&g_cnt_si[si], 1);
        atomicAdd(&g_cnt_di[di], 1);
    }
}

// exclusive prefix scan of per-dst degree -> CSR offsets. one block per relation.
__global__ __launch_bounds__(1024) void scan_kernel() {
    int which = blockIdx.x;
    const int* cnt = which ? g_cnt_di : g_cnt_du;
    int* off = which ? g_off1 : g_off0;
    __shared__ int wsum[32];
    __shared__ int carry;
    int tid = threadIdx.x, lane = tid & 31, wid = tid >> 5;
    if (tid == 0) carry = 0;
    __syncthreads();
    for (int base = 0; base < NN; base += 1024) {
        int i = base + tid;
        int v = (i < NN) ? cnt[i] : 0;
        int x = v;
        #pragma unroll
        for (int d = 1; d < 32; d <<= 1) {
            int y = __shfl_up_sync(0xffffffffu, x, d);
            if (lane >= d) x += y;
        }
        if (lane == 31) wsum[wid] = x;
        __syncthreads();
        if (wid == 0) {
            int s = wsum[lane];
            #pragma unroll
            for (int d = 1; d < 32; d <<= 1) {
                int y = __shfl_up_sync(0xffffffffu, s, d);
                if (lane >= d) s += y;
            }
            wsum[lane] = s;   // inclusive across warps
        }
        __syncthreads();
        int wprefix = (wid == 0) ? 0 : wsum[wid - 1];
        int excl = carry + wprefix + (x - v);
        if (i < NN) off[i] = excl;
        __syncthreads();
        if (tid == 0) carry += wsum[31];
        __syncthreads();
    }
}

// scatter edges into CSR order + precompute per-edge head bias float4
__global__ void scatter_kernel(const int* __restrict__ eui, const int* __restrict__ eiu,
                               const float* __restrict__ t_user, const float* __restrict__ t_item,
                               const float* __restrict__ hb, const float* __restrict__ beta,
                               const float* __restrict__ tau_raw,
                               const float* __restrict__ gamma, const float* __restrict__ delta) {
    int idx = blockIdx.x * blockDim.x + threadIdx.x;
    if (idx >= 2 * E) return;
    int r = (idx >= E) ? 1 : 0;
    int e = idx - r * E;
    const int* ei = r ? eiu : eui;
    int src = ei[e], dst = ei[e + E];
    int* cur = r ? g_cur1 : g_cur0;
    const int* off = r ? g_off1 : g_off0;
    int pos = off[dst] + atomicAdd(&cur[dst], 1);
    g_src_s[r * E + pos] = src;

    float ts = (r ? t_item : t_user)[src];
    float td = (r ? t_user : t_item)[dst];
    float dt = fabsf(td - ts) + 1e-6f;
    int pid = src * 40000 + dst;
    float cntf = (float)(ht_query(r, pid) - 1);
    float recf = (ht_query(2 + r, pid) > 0) ? 1.f : 0.f;
    float tau = log1pf(expf(tau_raw[r])) + 1e-6f;
    float a = -log1pf(dt / tau);
    float b = log1pf(cntf);
    float4 bias;
    bias.x = hb[r * H + 0] + a * beta[r * H + 0] + b * gamma[r * H + 0] + recf * delta[r * H + 0];
    bias.y = hb[r * H + 1] + a * beta[r * H + 1] + b * gamma[r * H + 1] + recf * delta[r * H + 1];
    bias.z = hb[r * H + 2] + a * beta[r * H + 2] + b * gamma[r * H + 2] + recf * delta[r * H + 2];
    bias.w = hb[r * H + 3] + a * beta[r * H + 3] + b * gamma[r * H + 3] + recf * delta[r * H + 3];
    g_bias4[r * E + pos] = bias;
}

// fused edge attention: warp per destination, online softmax + weighted-V accumulate.
__global__ __launch_bounds__(256) void attn_kernel() {
    int n = (blockIdx.x * blockDim.x + threadIdx.x) >> 5;
    int lane = threadIdx.x & 31;
    int r = blockIdx.y;
    if (n >= NN) return;

    const float* Q     = g_proj + (size_t)(r == 0 ? 3 : 0) * NN * C + (size_t)n * C;
    const float* Kbase = g_proj + (size_t)(r == 0 ? 1 : 4) * NN * C;
    const float* Vbase = g_proj + (size_t)(r == 0 ? 2 : 5) * NN * C;
    const int* off = r ? g_off1 : g_off0;
    int s0 = off[n];
    int s1 = (n + 1 < NN) ? off[n + 1] : E;
    const int* srcs = g_src_s + r * E;
    const float4* bias = g_bias4 + r * E;

    float4 q = *(const float4*)(Q + lane * 4);
    int h = lane >> 3;

    float m = -INFINITY, z = 0.f;
    float a0 = 0.f, a1 = 0.f, a2 = 0.f, a3 = 0.f;

    for (int j = s0; j < s1; j++) {
        int src = srcs[j];
        const float4 k = *(const float4*)(Kbase + (size_t)src * C + lane * 4);
        float p = q.x * k.x + q.y * k.y + q.z * k.z + q.w * k.w;
        p += __shfl_xor_sync(0xffffffffu, p, 1);
        p += __shfl_xor_sync(0xffffffffu, p, 2);
        p += __shfl_xor_sync(0xffffffffu, p, 4);   // 8-lane group = this head's dot

        float4 b4 = bias[j];
        float bh = (h == 0) ? b4.x : (h == 1) ? b4.y : (h == 2) ? b4.z : b4.w;
        float s = p * 0.1767766952966369f + bh;

        float mn = fmaxf(m, s);
        float fac = __expf(m - mn);     // first iter: exp(-inf) = 0
        float es  = __expf(s - mn);
        z = z * fac + es;
        const float4 v = *(const float4*)(Vbase + (size_t)src * C + lane * 4);
        a0 = a0 * fac + es * v.x;
        a1 = a1 * fac + es * v.y;
        a2 = a2 * fac + es * v.z;
        a3 = a3 * fac + es * v.w;
        m = mn;
    }

    float inv = (z > 0.f) ? 1.f / z : 0.f;
    __nv_bfloat16* ag = g_aggb + (size_t)r * NN * C + (size_t)n * C + lane * 4;
    *(__nv_bfloat162*)(ag)     = __float22bfloat162_rn(make_float2(a0 * inv, a1 * inv));
    *(__nv_bfloat162*)(ag + 2) = __float22bfloat162_rn(make_float2(a2 * inv, a3 * inv));
}

// ------------- bf16 tensor-core GEMM (bf16 inputs): C = A @ W^T (+bias) -------------
struct GemmJobB { const __nv_bfloat16* A; const __nv_bfloat16* W; const float* bias; float* out; };
struct GemmJobsB6 { GemmJobB j[6]; };

#define BSM_STRIDE 136   // bf16 elems per row: 17 x 16B -> ldmatrix conflict-free
#define BSM_BYTES (2 * 128 * BSM_STRIDE * 2)   // 69632 B

// shared tile loader: global bf16 [rows][128] -> smem [128][136]
__device__ __forceinline__ void load_tile_bf16(__nv_bfloat16* dstA, const __nv_bfloat16* A,
                                               __nv_bfloat16* dstW, const __nv_bfloat16* W,
                                               int tid) {
    #pragma unroll 4
    for (int i = tid; i < 128 * 16; i += 256) {
        int r = i >> 4, c8 = (i & 15) << 3;
        *(uint4*)(dstA + r * BSM_STRIDE + c8) = *(const uint4*)(A + r * 128 + c8);
        *(uint4*)(dstW + r * BSM_STRIDE + c8) = *(const uint4*)(W + r * 128 + c8);
    }
}

// fragment loader for one k16-step
__device__ __forceinline__ void load_frags(const uint32_t aAddr[2], const uint32_t bAddr[4],
                                           uint32_t koff, uint32_t a[2][4], uint32_t b[8][2]) {
    ldsm4(a[0][0], a[0][1], a[0][2], a[0][3], aAddr[0] + koff);
    ldsm4(a[1][0], a[1][1], a[1][2], a[1][3], aAddr[1] + koff);
    #pragma unroll
    for (int ntp = 0; ntp < 4; ntp++)
        ldsm4(b[2 * ntp][0], b[2 * ntp][1], b[2 * ntp + 1][0], b[2 * ntp + 1][1],
              bAddr[ntp] + koff);
}

// core 128x128x128 compute, software-pipelined (double-buffered fragments)
__device__ __forceinline__ void gemm_core(const __nv_bfloat16* As, const __nv_bfloat16* Ws,
                                          int warp, int lane, float acc[2][8][4]) {
    int wm = warp >> 1, wn = warp & 1;
    uint32_t sA = (uint32_t)__cvta_generic_to_shared(As);
    uint32_t sW = (uint32_t)__cvta_generic_to_shared(Ws);
    uint32_t aAddr[2], bAddr[4];
    #pragma unroll
    for (int mt = 0; mt < 2; mt++) {
        int row = wm * 32 + mt * 16 + (lane & 15);
        int col = (lane >> 4) << 3;
        aAddr[mt] = sA + (row * BSM_STRIDE + col) * 2;
    }
    #pragma unroll
    for (int ntp = 0; ntp < 4; ntp++) {
        int row = wn * 64 + ntp * 16 + ((lane >> 4) << 3) + (lane & 7);
        int col = ((lane >> 3) & 1) << 3;
        bAddr[ntp] = sW + (row * BSM_STRIDE + col) * 2;
    }

    uint32_t a[2][2][4], b[2][8][2];
    load_frags(aAddr, bAddr, 0, a[0], b[0]);
    #pragma unroll
    for (int ks = 0; ks < 8; ks++) {
        int cur = ks & 1;
        if (ks < 7)
            load_frags(aAddr, bAddr, (uint32_t)(ks + 1) * 32, a[cur ^ 1], b[cur ^ 1]);
        #pragma unroll
        for (int mt = 0; mt < 2; mt++)
            #pragma unroll
            for (int nt = 0; nt < 8; nt++)
                mma_bf16(acc[mt][nt], a[cur][mt], b[cur][nt]);
    }
}

__global__ __launch_bounds__(256, 2) void gemm_bf16_kernel(GemmJobsB6 jobs, int M) {
    const GemmJobB jb = jobs.j[blockIdx.y];
    extern __shared__ __nv_bfloat16 shb[];
    __nv_bfloat16* As = shb;
    __nv_bfloat16* Ws = shb + 128 * BSM_STRIDE;
    int tid = threadIdx.x;
    int row0 = blockIdx.x * 128;

    load_tile_bf16(As, jb.A + (size_t)row0 * 128, Ws, jb.W, tid);
    __syncthreads();

    int warp = tid >> 5, lane = tid & 31;
    int wm = warp >> 1, wn = warp & 1;
    int g = lane >> 2, t4 = lane & 3;

    float acc[2][8][4];
    #pragma unroll
    for (int mt = 0; mt < 2; mt++)
        #pragma unroll
        for (int nt = 0; nt < 8; nt++)
            #pragma unroll
            for (int q = 0; q < 4; q++) acc[mt][nt][q] = 0.f;

    gemm_core(As, Ws, warp, lane, acc);

    #pragma unroll
    for (int mt = 0; mt < 2; mt++) {
        #pragma unroll
        for (int half = 0; half < 2; half++) {
            int row = row0 + wm * 32 + mt * 16 + g + half * 8;
            if (row >= M) continue;
            float* orow = jb.out + (size_t)row * 128 + wn * 64;
            #pragma unroll
            for (int nt = 0; nt < 8; nt++) {
                int col = nt * 8 + t4 * 2;
                float b0 = 0.f, b1 = 0.f;
                if (jb.bias) {
                    b0 = jb.bias[wn * 64 + col];
                    b1 = jb.bias[wn * 64 + col + 1];
                }
                float2 o = make_float2(acc[mt][nt][half * 2 + 0] + b0,
                                       acc[mt][nt][half * 2 + 1] + b1);
                *(float2*)(orow + col) = o;
            }
        }
    }
}

// final: out = LayerNorm(proj + indeg*bo + deg + x). one warp per node.
__global__ void final_kernel(const float* __restrict__ x_user, const float* __restrict__ x_item,
                             const float* __restrict__ bo, float* __restrict__ out) {
    int n = (blockIdx.x * blockDim.x + threadIdx.x) >> 5;
    int lane = threadIdx.x & 31;
    int ty = blockIdx.y;     // 0 = user, 1 = item
    if (n >= NN) return;
    float* o = out + (ty == 0 ? (size_t)0 : (size_t)NN * C) + (size_t)n * C;
    const float* x = (ty == 0 ? x_user : x_item) + (size_t)n * C;
    float indeg = (float)(ty == 0 ? g_cnt_di[n] : g_cnt_du[n]);
    float deg = (float)(ty == 0 ? (g_cnt_su[n] + g_cnt_di[n])
                                : (g_cnt_du[n] + g_cnt_si[n]));
    float4 v  = *(float4*)(o + lane * 4);
    float4 xv = *(const float4*)(x + lane * 4);
    float4 bv = *(const float4*)(bo + lane * 4);
    v.x += xv.x + indeg * bv.x + deg;
    v.y += xv.y + indeg * bv.y + deg;
    v.z += xv.z + indeg * bv.z + deg;
    v.w += xv.w + indeg * bv.w + deg;
    float s = v.x + v.y + v.z + v.w;
    #pragma unroll
    for (int d = 16; d; d >>= 1) s += __shfl_xor_sync(0xffffffffu, s, d);
    float mu = s * (1.f / 128.f);
    float d0 = v.x - mu, d1 = v.y - mu, d2 = v.z - mu, d3 = v.w - mu;
    float q = d0 * d0 + d1 * d1 + d2 * d2 + d3 * d3;
    #pragma unroll
    for (int d = 16; d; d >>= 1) q += __shfl_xor_sync(0xffffffffu, q, d);
    float inv = 1.f / sqrtf(q * (1.f / 128.f) + 1e-5f);
    float4 r4 = make_float4(d0 * inv, d1 * inv, d2 * inv, d3 * inv);
    *(float4*)(o + lane * 4) = r4;
}

// ---------------- launch ----------------
extern "C" void kernel_launch(void* const* d_in, const int* in_sizes, int n_in,
                              void* d_out, int out_size) {
    const float* x_user  = (const float*)d_in[0];
    const float* x_item  = (const float*)d_in[1];
    const float* t_user  = (const float*)d_in[2];
    const float* t_item  = (const float*)d_in[3];
    const int*   eui     = (const int*)d_in[4];
    const int*   eiu     = (const int*)d_in[5];
    const float* Wq      = (const float*)d_in[6];
    const float* bq      = (const float*)d_in[7];
    const float* Wk      = (const float*)d_in[8];
    const float* bk      = (const float*)d_in[9];
    const float* Wv      = (const float*)d_in[10];
    const float* bv      = (const float*)d_in[11];
    const float* Wo      = (const float*)d_in[12];
    const float* bo      = (const float*)d_in[13];
    const float* hb      = (const float*)d_in[14];
    const float* beta    = (const float*)d_in[15];
    const float* tau_raw = (const float*)d_in[16];
    const float* gammaP  = (const float*)d_in[17];
    const float* deltaP  = (const float*)d_in[18];
    float* out = (float*)d_out;

    float* proj;
    __nv_bfloat16 *xb, *wb, *aggb;
    cudaGetSymbolAddress((void**)&proj, g_proj);
    cudaGetSymbolAddress((void**)&xb, g_xb);
    cudaGetSymbolAddress((void**)&wb, g_wb);
    cudaGetSymbolAddress((void**)&aggb, g_aggb);

    cudaFuncSetAttribute(gemm_bf16_kernel,
                         cudaFuncAttributeMaxDynamicSharedMemorySize, BSM_BYTES);

    int gblocks = (NN + 127) / 128;   // 313

    // 1: convert+clear  2: build_ht  3: scan  4: QKV gemm (profiled)
    // 5: scatter  6: attn  7: O gemm  8: final
    convert_clear_kernel<<<512, 256>>>(x_user, x_item, Wq, Wk, Wv, Wo);
    build_ht_kernel<<<(2 * E + 255) / 256, 256>>>(eui, eiu);
    scan_kernel<<<2, 1024>>>();

    GemmJobsB6 qkv;
    qkv.j[0] = { xb,          wb,             bq, proj + (size_t)0 * NN * C };
    qkv.j[1] = { xb,          wb + C * C,     bk, proj + (size_t)1 * NN * C };
    qkv.j[2] = { xb,          wb + 2 * C * C, bv, proj + (size_t)2 * NN * C };
    qkv.j[3] = { xb + NN * C, wb,             bq, proj + (size_t)3 * NN * C };
    qkv.j[4] = { xb + NN * C, wb + C * C,     bk, proj + (size_t)4 * NN * C };
    qkv.j[5] = { xb + NN * C, wb + 2 * C * C, bv, proj + (size_t)5 * NN * C };
    gemm_bf16_kernel<<<dim3(gblocks, 6), 256, BSM_BYTES>>>(qkv, NN);

    scatter_kernel<<<(2 * E + 255) / 256, 256>>>(eui, eiu, t_user, t_item,
                                                 hb, beta, tau_raw, gammaP, deltaP);

    dim3 agrid((NN * 32 + 255) / 256, 2);
    attn_kernel<<<agrid, 256>>>();

    // relation 0 (user->item) feeds out_item; relation 1 feeds out_user
    GemmJobsB6 ojobs;
    ojobs.j[0] = { aggb,          wb + 3 * C * C, nullptr, out + (size_t)NN * C };
    ojobs.j[1] = { aggb + NN * C, wb + 3 * C * C, nullptr, out };
    ojobs.j[2] = ojobs.j[0]; ojobs.j[3] = ojobs.j[0];
    ojobs.j[4] = ojobs.j[0]; ojobs.j[5] = ojobs.j[0];
    gemm_bf16_kernel<<<dim3(gblocks, 2), 256, BSM_BYTES>>>(ojobs, NN);

    dim3 fgrid((NN * 32 + 255) / 256, 2);
    final_kernel<<<fgrid, 256>>>(x_user, x_item, bo, out);
}